// round 14
// baseline (speedup 1.0000x reference)
#include <cuda_runtime.h>
#include <cuda_fp16.h>
#include <cuda.h>
#include <cstdint>

#define B_  32
#define T_  512
#define D_  512
#define E_  8
#define H_  2048

// ---------------------------------------------------------------------------
// Device scratch + dependency counters
// ---------------------------------------------------------------------------
__device__ int    g_chosen[B_];
__device__ int    g_prep_done;
__device__ int    g_done1[B_];      // GEMM1 tiles done per batch (target 64)
__device__ int    g_w2done;         // W2 convert blocks done (target 256)
__device__ float  g_pool_part[B_ * 32 * D_];
__device__ __half g_x_h[(size_t)B_ * T_ * D_];            // 16 MB
__device__ __half g_h_h[(size_t)B_ * T_ * H_];            // 64 MB
__device__ __half g_W1h[(size_t)E_ * D_ * H_];            // [E][D][H]
__device__ __half g_W2h[(size_t)E_ * H_ * D_];            // [E][H][D]

// ---------------------------------------------------------------------------
// PTX helpers
// ---------------------------------------------------------------------------
__device__ __forceinline__ uint32_t smem_to_u32(const void* p) {
    uint32_t a;
    asm("{ .reg .u64 t; cvta.to.shared.u64 t, %1; cvt.u32.u64 %0, t; }"
        : "=r"(a) : "l"(p));
    return a;
}

__device__ __forceinline__ void ldsm4(uint32_t* d, uint32_t addr) {
    asm volatile("ldmatrix.sync.aligned.m8n8.x4.shared.b16 {%0,%1,%2,%3}, [%4];"
                 : "=r"(d[0]), "=r"(d[1]), "=r"(d[2]), "=r"(d[3])
                 : "r"(addr));
}
__device__ __forceinline__ void ldsm4t(uint32_t* d, uint32_t addr) {
    asm volatile("ldmatrix.sync.aligned.m8n8.x4.trans.shared.b16 {%0,%1,%2,%3}, [%4];"
                 : "=r"(d[0]), "=r"(d[1]), "=r"(d[2]), "=r"(d[3])
                 : "r"(addr));
}
__device__ __forceinline__ void mma16816(float* c, const uint32_t* a,
                                         const uint32_t* b) {
    asm volatile(
        "mma.sync.aligned.m16n8k16.row.col.f32.f16.f16.f32 "
        "{%0,%1,%2,%3}, {%4,%5,%6,%7}, {%8,%9}, {%0,%1,%2,%3};"
        : "+f"(c[0]), "+f"(c[1]), "+f"(c[2]), "+f"(c[3])
        : "r"(a[0]), "r"(a[1]), "r"(a[2]), "r"(a[3]),
          "r"(b[0]), "r"(b[1]));
}

#define MBARRIER_INIT(addr, count) \
    asm volatile("mbarrier.init.shared.b64 [%0], %1;" \
        :: "r"((uint32_t)(addr)), "r"((uint32_t)(count)) : "memory")
#define MBARRIER_EXPECT_TX(addr, bytes) \
    asm volatile("mbarrier.arrive.expect_tx.shared.b64 _, [%0], %1;" \
        :: "r"((uint32_t)(addr)), "r"((uint32_t)(bytes)) : "memory")
#define MBARRIER_WAIT_PARITY(mbar_smem_addr, phase_parity) do { \
    uint32_t _mbar = (uint32_t)(mbar_smem_addr); \
    uint32_t _parity = (uint32_t)(phase_parity); \
    uint32_t _done; \
    asm volatile("{\n\t.reg .pred p;\n\t" \
        "mbarrier.try_wait.parity.acquire.cta.shared::cta.b64 p, [%1], %2;\n\t" \
        "selp.b32 %0, 1, 0, p;\n\t}" \
        : "=r"(_done) : "r"(_mbar), "r"(_parity) : "memory"); \
    if (!_done) { \
        asm volatile("{\n\t.reg .pred P1;\n\t" \
            "WAIT_LOOP_%=:\n\t" \
            "mbarrier.try_wait.parity.acquire.cta.shared::cta.b64 P1, [%0], %1, 0x989680;\n\t" \
            "@P1 bra.uni WAIT_DONE_%=;\n\t" \
            "bra.uni WAIT_LOOP_%=;\n\t" \
            "WAIT_DONE_%=:\n\t}" \
            :: "r"(_mbar), "r"(_parity) : "memory"); \
    } \
} while (0)

#define TMA_LOAD_3D(smem_addr, tmap_ptr, c0, c1, c2, mbar) \
    asm volatile("cp.async.bulk.tensor.3d.shared::cta.global.tile.mbarrier::complete_tx::bytes " \
        "[%0], [%1, {%2, %3, %4}], [%5];" \
        :: "r"((uint32_t)(smem_addr)), "l"(tmap_ptr), \
           "r"((int32_t)(c0)), "r"((int32_t)(c1)), "r"((int32_t)(c2)), \
           "r"((uint32_t)(mbar)) : "memory")

// ---------------------------------------------------------------------------
// Kernel 1: merged prep, grid (32, 32, 3), 256 threads.
//   z==0: x -> fp16 + pooled partials.
//   z==1 (g<512): streaming convert W1 f32 -> fp16.
//   z==2 (y==0, x<32): router for batch x, gated on all z==0 blocks done.
//        Block x==0 also resets the fused kernel's dependency counters.
// ---------------------------------------------------------------------------
__global__ __launch_bounds__(256)
void prep_kernel(const float* __restrict__ x,
                 __half* __restrict__ xh,
                 float* __restrict__ pool_part,
                 const float* __restrict__ W1,
                 __half* __restrict__ W1h,
                 const float* __restrict__ Wp,
                 const float* __restrict__ bp,
                 float* __restrict__ probs_out,
                 float* __restrict__ chosen_out)
{
    if (blockIdx.z == 0) {
        const int b  = blockIdx.x;
        const int tc = blockIdx.y;
        const int d0 = threadIdx.x * 2;

        float s0 = 0.0f, s1 = 0.0f;
        #pragma unroll 4
        for (int r = 0; r < 16; ++r) {
            const int t = tc * 16 + r;
            const size_t off = ((size_t)b * T_ + t) * D_ + d0;
            const float2 v = *reinterpret_cast<const float2*>(x + off);
            s0 += v.x; s1 += v.y;
            *reinterpret_cast<__half2*>(xh + off) =
                __halves2half2(__float2half_rn(v.x), __float2half_rn(v.y));
        }
        *reinterpret_cast<float2*>(pool_part + ((size_t)b * 32 + tc) * D_ + d0) =
            make_float2(s0, s1);
        __threadfence();
        __syncthreads();
        if (threadIdx.x == 0) atomicAdd(&g_prep_done, 1);
        return;
    }

    if (blockIdx.z == 2) {
        if (blockIdx.y != 0 || blockIdx.x >= B_) return;
        const int b = blockIdx.x;

        // counter resets for the fused kernel (stream-ordered before it)
        if (b == 0) {
            if (threadIdx.x < B_)  g_done1[threadIdx.x] = 0;
            if (threadIdx.x == 32) g_w2done = 0;
        }

        if (threadIdx.x == 0) {
            while (*(volatile int*)&g_prep_done < 32 * 32) __nanosleep(100);
        }
        __syncthreads();
        __threadfence();

        __shared__ float pooled[D_];
        __shared__ float logits[E_];
        #pragma unroll
        for (int k = 0; k < 2; ++k) {
            const int d = threadIdx.x + k * 256;
            float s = 0.0f;
            #pragma unroll
            for (int p = 0; p < 32; ++p)
                s += pool_part[((size_t)b * 32 + p) * D_ + d];
            pooled[d] = s * (1.0f / (float)T_);
        }
        __syncthreads();

        const int warp = threadIdx.x >> 5, lane = threadIdx.x & 31;
        {
            float s = 0.0f;
            #pragma unroll
            for (int k = 0; k < 16; ++k) {
                const int dd = lane + k * 32;
                s += pooled[dd] * Wp[dd * E_ + warp];
            }
            #pragma unroll
            for (int off = 16; off > 0; off >>= 1)
                s += __shfl_down_sync(0xffffffffu, s, off);
            if (lane == 0) logits[warp] = s + bp[warp];
        }
        __syncthreads();

        if (threadIdx.x == 0) {
            float m = logits[0]; int arg = 0;
            #pragma unroll
            for (int e = 1; e < E_; ++e)
                if (logits[e] > m) { m = logits[e]; arg = e; }
            float ex[E_], sum = 0.0f;
            #pragma unroll
            for (int e = 0; e < E_; ++e) { ex[e] = expf(logits[e] - m); sum += ex[e]; }
            const float inv = 1.0f / sum;
            if (probs_out) {
                #pragma unroll
                for (int e = 0; e < E_; ++e) probs_out[b * E_ + e] = ex[e] * inv;
            }
            if (chosen_out) chosen_out[b] = (float)arg;
            g_chosen[b] = arg;
        }
        return;
    }

    // ---- z==1: streaming W1 convert (first 512 blocks only) ----
    {
        const int g = blockIdx.y * 32 + blockIdx.x;
        if (g >= 512) return;
        const float* src = W1 + (size_t)g * 16384;
        __half* dst = W1h + (size_t)g * 16384;
        #pragma unroll
        for (int i = 0; i < 16; ++i) {
            const int idx = (threadIdx.x + i * 256) * 4;
            const float4 v = *reinterpret_cast<const float4*>(src + idx);
            __half2 h0 = __halves2half2(__float2half_rn(v.x), __float2half_rn(v.y));
            __half2 h1 = __halves2half2(__float2half_rn(v.z), __float2half_rn(v.w));
            uint2 pk;
            pk.x = *reinterpret_cast<uint32_t*>(&h0);
            pk.y = *reinterpret_cast<uint32_t*>(&h1);
            *reinterpret_cast<uint2*>(dst + idx) = pk;
        }
    }
}

// ---------------------------------------------------------------------------
// GEMM tile body (shared by both GEMMs): 128x128 CTA tile, 8 warps of 64x32,
// BK=64, 3-stage TMA+mbarrier pipeline.
// ---------------------------------------------------------------------------
#define STAGE_BYTES 32768
#define MBAR_OFF    (3 * STAGE_BYTES)
#define GEMM_SMEM   (MBAR_OFF + 128)

__device__ __forceinline__ void gemm_tile(
    const CUtensorMap* tmA, const CUtensorMap* tmB,
    const float* __restrict__ biasAll,
    float* outF, __half* outH,
    int K, int Nt, int b, int e, int m0, int n0,
    bool g1, char* smem)
{
    const uint32_t sbase = smem_to_u32(smem);
    const int tid  = threadIdx.x;
    const int lane = tid & 31;
    const int wid  = tid >> 5;
    const int warp_m = wid & 1;
    const int warp_n = wid >> 1;

    const int ltile = lane >> 3;
    const int lr    = lane & 7;
    const uint32_t xr = (uint32_t)lr << 4;
    const uint32_t baseA = (uint32_t)(warp_m * 64 + (ltile & 1) * 8 + lr) * 128u;
    const uint32_t kcA   = (uint32_t)(ltile >> 1) * 16u;

    const uint32_t bOff = 16384u + (uint32_t)(warp_n >> 1) * 8192u;
    const uint32_t rowL = (uint32_t)((ltile & 1) * 8 + lr);
    const uint32_t cb0  = (uint32_t)((warp_n & 1) * 4 + (ltile >> 1));
    const uint32_t addrB0 = bOff + rowL * 128u + ((cb0 ^ (uint32_t)lr) << 4);
    const uint32_t addrB1 = bOff + rowL * 128u + (((cb0 + 2u) ^ (uint32_t)lr) << 4);

    float acc[4][4][4];
    #pragma unroll
    for (int mi = 0; mi < 4; ++mi)
        #pragma unroll
        for (int ni = 0; ni < 4; ++ni)
            #pragma unroll
            for (int i = 0; i < 4; ++i) acc[mi][ni][i] = 0.0f;

    const int KB = K >> 6;
    const uint32_t mbar0 = sbase + MBAR_OFF;

    auto issue_stage = [&](int s, int kb2) {
        const uint32_t stg = sbase + (uint32_t)s * STAGE_BYTES;
        const uint32_t mb  = mbar0 + (uint32_t)s * 8u;
        const int k0 = kb2 << 6;
        MBARRIER_EXPECT_TX(mb, STAGE_BYTES);
        TMA_LOAD_3D(stg,           tmA, k0,       m0, b, mb);
        TMA_LOAD_3D(stg + 16384u,  tmB, n0,       k0, e, mb);
        TMA_LOAD_3D(stg + 24576u,  tmB, n0 + 64,  k0, e, mb);
    };

    if (tid == 0) {
        MBARRIER_INIT(mbar0 + 0, 1);
        MBARRIER_INIT(mbar0 + 8, 1);
        MBARRIER_INIT(mbar0 + 16, 1);
        asm volatile("fence.proxy.async.shared::cta;" ::: "memory");
    }
    __syncthreads();
    if (tid == 0) {
        issue_stage(0, 0);
        issue_stage(1, 1);
    }

    uint32_t af[2][4][4], bf[4][2];

    auto load_af = [&](int buf, uint32_t stg, int kk) {
        const uint32_t kA = ((uint32_t)(kk * 32) + kcA) ^ xr;
        #pragma unroll
        for (int mi = 0; mi < 4; ++mi)
            ldsm4(af[buf][mi], stg + baseA + mi * 2048u + kA);
    };
    auto load_bf = [&](uint32_t stg, int kk) {
        const uint32_t kOff = (uint32_t)kk * 2048u;
        uint32_t t4[4];
        ldsm4t(t4, stg + kOff + addrB0);
        bf[0][0] = t4[0]; bf[0][1] = t4[1];
        bf[1][0] = t4[2]; bf[1][1] = t4[3];
        ldsm4t(t4, stg + kOff + addrB1);
        bf[2][0] = t4[0]; bf[2][1] = t4[1];
        bf[3][0] = t4[2]; bf[3][1] = t4[3];
    };

    for (int kb = 0; kb < KB; ++kb) {
        const int s = kb % 3;
        const int par = (kb / 3) & 1;
        MBARRIER_WAIT_PARITY(mbar0 + (uint32_t)s * 8u, par);
        if (tid == 0 && kb + 2 < KB) issue_stage((kb + 2) % 3, kb + 2);

        const uint32_t stg = sbase + (uint32_t)s * STAGE_BYTES;

        load_af(0, stg, 0);
        #pragma unroll
        for (int kk = 0; kk < 4; ++kk) {
            load_bf(stg, kk);
            if (kk < 3) load_af((kk + 1) & 1, stg, kk + 1);
            #pragma unroll
            for (int mi = 0; mi < 4; ++mi)
                #pragma unroll
                for (int ni = 0; ni < 4; ++ni)
                    mma16816(acc[mi][ni], af[kk & 1][mi], bf[ni]);
        }
        __syncthreads();
    }

    // ---- epilogue ----
    const int gm = m0 + warp_m * 64;
    const int gncol = n0 + warp_n * 32;
    #pragma unroll
    for (int mi = 0; mi < 4; ++mi) {
        const int row0 = gm + mi * 16 + (lane >> 2);
        #pragma unroll
        for (int ni = 0; ni < 4; ++ni) {
            const int col = gncol + ni * 8 + (lane & 3) * 2;
            const float2 bv = *reinterpret_cast<const float2*>(
                biasAll + (size_t)e * Nt + col);
            float v00 = acc[mi][ni][0] + bv.x;
            float v01 = acc[mi][ni][1] + bv.y;
            float v10 = acc[mi][ni][2] + bv.x;
            float v11 = acc[mi][ni][3] + bv.y;
            const size_t o0 = ((size_t)b * T_ + row0) * Nt + col;
            const size_t o1 = ((size_t)b * T_ + row0 + 8) * Nt + col;
            if (g1) {
                v00 = fmaxf(v00, 0.0f); v01 = fmaxf(v01, 0.0f);
                v10 = fmaxf(v10, 0.0f); v11 = fmaxf(v11, 0.0f);
                *reinterpret_cast<__half2*>(outH + o0) =
                    __halves2half2(__float2half_rn(v00), __float2half_rn(v01));
                *reinterpret_cast<__half2*>(outH + o1) =
                    __halves2half2(__float2half_rn(v10), __float2half_rn(v11));
            } else {
                *reinterpret_cast<float2*>(outF + o0) = make_float2(v00, v01);
                *reinterpret_cast<float2*>(outF + o1) = make_float2(v10, v11);
            }
        }
    }
}

// ---------------------------------------------------------------------------
// Kernel 2: fused W2-convert + GEMM1 + GEMM2, 1D grid of 2816 one-tile CTAs.
// Bid order = topological order: [256 W2conv][2048 GEMM1 b-major][512 GEMM2
// b-major]. GEMM2 gates on per-batch GEMM1 completion + W2 conversion.
// ---------------------------------------------------------------------------
#define NW2C   256
#define NG1    2048
#define NG2    512

__global__ __launch_bounds__(256, 2)
void moe_fused_kernel(const __grid_constant__ CUtensorMap tmA1,
                      const __grid_constant__ CUtensorMap tmB1,
                      const __grid_constant__ CUtensorMap tmA2,
                      const __grid_constant__ CUtensorMap tmB2,
                      const float* __restrict__ b1,
                      const float* __restrict__ b2,
                      __half* __restrict__ hh,
                      float* __restrict__ outFinal,
                      const float* __restrict__ W2src,
                      __half* __restrict__ W2h)
{
    extern __shared__ char smem[];
    const int bid = blockIdx.x;

    if (bid < NW2C) {
        // ---- W2 streaming convert: 256 blocks x 32768 f32 ----
        if (bid == 0 && threadIdx.x == 0) g_prep_done = 0;   // replay reset
        const float* src = W2src + (size_t)bid * 32768;
        __half* dst = W2h + (size_t)bid * 32768;
        #pragma unroll
        for (int i = 0; i < 32; ++i) {
            const int idx = (threadIdx.x + i * 256) * 4;
            const float4 v = *reinterpret_cast<const float4*>(src + idx);
            __half2 h0 = __halves2half2(__float2half_rn(v.x), __float2half_rn(v.y));
            __half2 h1 = __halves2half2(__float2half_rn(v.z), __float2half_rn(v.w));
            uint2 pk;
            pk.x = *reinterpret_cast<uint32_t*>(&h0);
            pk.y = *reinterpret_cast<uint32_t*>(&h1);
            *reinterpret_cast<uint2*>(dst + idx) = pk;
        }
        __threadfence();
        __syncthreads();
        if (threadIdx.x == 0) atomicAdd(&g_w2done, 1);
        return;
    }

    if (bid < NW2C + NG1) {
        // ---- GEMM1 tile: h = relu(x @ W1[e] + b1[e]), batch-major ----
        const int t  = bid - NW2C;
        const int b  = t >> 6;
        const int rm = t & 63;
        const int m0 = (rm >> 4) * 128;
        const int n0 = (rm & 15) * 128;
        const int e  = g_chosen[b];
        gemm_tile(&tmA1, &tmB1, b1, nullptr, hh, D_, H_,
                  b, e, m0, n0, true, smem);
        __threadfence();
        __syncthreads();
        if (threadIdx.x == 0) atomicAdd(&g_done1[b], 1);
        return;
    }

    // ---- GEMM2 tile: final = h @ W2[e] + b2[e], gated ----
    const int t  = bid - NW2C - NG1;
    const int b  = t >> 4;
    const int rm = t & 15;
    const int m0 = (rm >> 2) * 128;
    const int n0 = (rm & 3) * 128;
    if (threadIdx.x == 0) {
        while (*(volatile int*)&g_w2done < NW2C) __nanosleep(64);
        while (((volatile int*)g_done1)[b] < 64) __nanosleep(64);
    }
    __syncthreads();
    __threadfence();
    const int e = g_chosen[b];
    gemm_tile(&tmA2, &tmB2, b2, outFinal, nullptr, H_, D_,
              b, e, m0, n0, false, smem);
}

// ---------------------------------------------------------------------------
// Host: tensormap encoding via driver entry point
// ---------------------------------------------------------------------------
typedef CUresult (*EncFn)(CUtensorMap*, CUtensorMapDataType, cuuint32_t, void*,
                          const cuuint64_t*, const cuuint64_t*, const cuuint32_t*,
                          const cuuint32_t*, CUtensorMapInterleave,
                          CUtensorMapSwizzle, CUtensorMapL2promotion,
                          CUtensorMapFloatOOBfill);

static EncFn get_encoder()
{
    void* fn = nullptr;
    cudaDriverEntryPointQueryResult st;
#if CUDART_VERSION >= 12050
    cudaGetDriverEntryPointByVersion("cuTensorMapEncodeTiled", &fn, 12000,
                                     cudaEnableDefault, &st);
#else
    cudaGetDriverEntryPoint("cuTensorMapEncodeTiled", &fn,
                            cudaEnableDefault, &st);
#endif
    return (EncFn)fn;
}

static void make_tmap(EncFn enc, CUtensorMap* tm, void* base,
                      uint64_t d0, uint64_t d1, uint64_t d2,
                      uint32_t box0, uint32_t box1)
{
    cuuint64_t dims[3]    = {d0, d1, d2};
    cuuint64_t strides[2] = {d0 * 2, d0 * d1 * 2};
    cuuint32_t box[3]     = {box0, box1, 1};
    cuuint32_t es[3]      = {1, 1, 1};
    enc(tm, CU_TENSOR_MAP_DATA_TYPE_FLOAT16, 3, base, dims, strides, box, es,
        CU_TENSOR_MAP_INTERLEAVE_NONE, CU_TENSOR_MAP_SWIZZLE_128B,
        CU_TENSOR_MAP_L2_PROMOTION_L2_128B, CU_TENSOR_MAP_FLOAT_OOB_FILL_NONE);
}

// ---------------------------------------------------------------------------
// kernel_launch
// ---------------------------------------------------------------------------
extern "C" void kernel_launch(void* const* d_in, const int* in_sizes, int n_in,
                              void* d_out, int out_size)
{
    const float* x  = (const float*)d_in[0];
    const float* Wp = (const float*)d_in[1];
    const float* bp = (const float*)d_in[2];
    const float* W1 = (const float*)d_in[3];
    const float* b1 = (const float*)d_in[4];
    const float* W2 = (const float*)d_in[5];
    const float* b2 = (const float*)d_in[6];
    float* out = (float*)d_out;

    const long long FINAL_N = (long long)B_ * T_ * D_;
    float* probs_out  = nullptr;
    float* chosen_out = nullptr;
    if ((long long)out_size >= FINAL_N + (long long)B_ * E_)
        probs_out = out + FINAL_N;
    if ((long long)out_size >= FINAL_N + (long long)B_ * E_ + B_)
        chosen_out = out + FINAL_N + (long long)B_ * E_;

    __half *xh, *hh, *w1h, *w2h;
    float* pool_part;
    cudaGetSymbolAddress((void**)&xh, g_x_h);
    cudaGetSymbolAddress((void**)&hh, g_h_h);
    cudaGetSymbolAddress((void**)&w1h, g_W1h);
    cudaGetSymbolAddress((void**)&w2h, g_W2h);
    cudaGetSymbolAddress((void**)&pool_part, g_pool_part);

    EncFn enc = get_encoder();
    CUtensorMap tmA1, tmB1, tmA2, tmB2;
    make_tmap(enc, &tmA1, xh,  512, 512, 32, 64, 128);     // A1: (K,T,B)
    make_tmap(enc, &tmB1, w1h, 2048, 512, 8, 64, 64);      // B1: (N,K,E)
    make_tmap(enc, &tmA2, hh,  2048, 512, 32, 64, 128);    // A2
    make_tmap(enc, &tmB2, w2h, 512, 2048, 8, 64, 64);      // B2

    cudaFuncSetAttribute(moe_fused_kernel,
                         cudaFuncAttributeMaxDynamicSharedMemorySize, GEMM_SMEM);

    // 1) prep: x->fp16 + pool partials (z=0), W1 convert (z=1), router (z=2,
    //    also resets fused-kernel counters)
    prep_kernel<<<dim3(32, 32, 3), 256>>>(x, xh, pool_part, W1, w1h,
                                          Wp, bp, probs_out, chosen_out);

    // 2) fused: [W2 convert][GEMM1][GEMM2] with bid-order dependency gates
    moe_fused_kernel<<<NW2C + NG1 + NG2, 256, GEMM_SMEM>>>(
        tmA1, tmB1, tmA2, tmB2, b1, b2, hh, out, W2, w2h);
}

// round 16
// speedup vs baseline: 1.0311x; 1.0311x over previous
#include <cuda_runtime.h>
#include <cuda_fp16.h>
#include <cuda.h>
#include <cstdint>

#define B_  32
#define T_  512
#define D_  512
#define E_  8
#define H_  2048

// ---------------------------------------------------------------------------
// Device scratch
// ---------------------------------------------------------------------------
__device__ int    g_chosen[B_];
__device__ int    g_prep_done;
__device__ float  g_pool_part[B_ * 32 * D_];
__device__ __half g_x_h[(size_t)B_ * T_ * D_];            // 16 MB
__device__ __half g_h_h[(size_t)B_ * T_ * H_];            // 64 MB
__device__ __half g_W1h[(size_t)E_ * D_ * H_];            // [E][D][H]
__device__ __half g_W2h[(size_t)E_ * H_ * D_];            // [E][H][D]

// ---------------------------------------------------------------------------
// PTX helpers
// ---------------------------------------------------------------------------
__device__ __forceinline__ uint32_t smem_to_u32(const void* p) {
    uint32_t a;
    asm("{ .reg .u64 t; cvta.to.shared.u64 t, %1; cvt.u32.u64 %0, t; }"
        : "=r"(a) : "l"(p));
    return a;
}

__device__ __forceinline__ void ldsm4(uint32_t* d, uint32_t addr) {
    asm volatile("ldmatrix.sync.aligned.m8n8.x4.shared.b16 {%0,%1,%2,%3}, [%4];"
                 : "=r"(d[0]), "=r"(d[1]), "=r"(d[2]), "=r"(d[3])
                 : "r"(addr));
}
__device__ __forceinline__ void ldsm4t(uint32_t* d, uint32_t addr) {
    asm volatile("ldmatrix.sync.aligned.m8n8.x4.trans.shared.b16 {%0,%1,%2,%3}, [%4];"
                 : "=r"(d[0]), "=r"(d[1]), "=r"(d[2]), "=r"(d[3])
                 : "r"(addr));
}
__device__ __forceinline__ void mma16816(float* c, const uint32_t* a,
                                         const uint32_t* b) {
    asm volatile(
        "mma.sync.aligned.m16n8k16.row.col.f32.f16.f16.f32 "
        "{%0,%1,%2,%3}, {%4,%5,%6,%7}, {%8,%9}, {%0,%1,%2,%3};"
        : "+f"(c[0]), "+f"(c[1]), "+f"(c[2]), "+f"(c[3])
        : "r"(a[0]), "r"(a[1]), "r"(a[2]), "r"(a[3]),
          "r"(b[0]), "r"(b[1]));
}

#define GRIDDEP_WAIT() asm volatile("griddepcontrol.wait;" ::: "memory")

#define MBARRIER_INIT(addr, count) \
    asm volatile("mbarrier.init.shared.b64 [%0], %1;" \
        :: "r"((uint32_t)(addr)), "r"((uint32_t)(count)) : "memory")
#define MBARRIER_EXPECT_TX(addr, bytes) \
    asm volatile("mbarrier.arrive.expect_tx.shared.b64 _, [%0], %1;" \
        :: "r"((uint32_t)(addr)), "r"((uint32_t)(bytes)) : "memory")
#define MBARRIER_WAIT_PARITY(mbar_smem_addr, phase_parity) do { \
    uint32_t _mbar = (uint32_t)(mbar_smem_addr); \
    uint32_t _parity = (uint32_t)(phase_parity); \
    uint32_t _done; \
    asm volatile("{\n\t.reg .pred p;\n\t" \
        "mbarrier.try_wait.parity.acquire.cta.shared::cta.b64 p, [%1], %2;\n\t" \
        "selp.b32 %0, 1, 0, p;\n\t}" \
        : "=r"(_done) : "r"(_mbar), "r"(_parity) : "memory"); \
    if (!_done) { \
        asm volatile("{\n\t.reg .pred P1;\n\t" \
            "WAIT_LOOP_%=:\n\t" \
            "mbarrier.try_wait.parity.acquire.cta.shared::cta.b64 P1, [%0], %1, 0x989680;\n\t" \
            "@P1 bra.uni WAIT_DONE_%=;\n\t" \
            "bra.uni WAIT_LOOP_%=;\n\t" \
            "WAIT_DONE_%=:\n\t}" \
            :: "r"(_mbar), "r"(_parity) : "memory"); \
    } \
} while (0)

#define TMA_LOAD_3D(smem_addr, tmap_ptr, c0, c1, c2, mbar) \
    asm volatile("cp.async.bulk.tensor.3d.shared::cta.global.tile.mbarrier::complete_tx::bytes " \
        "[%0], [%1, {%2, %3, %4}], [%5];" \
        :: "r"((uint32_t)(smem_addr)), "l"(tmap_ptr), \
           "r"((int32_t)(c0)), "r"((int32_t)(c1)), "r"((int32_t)(c2)), \
           "r"((uint32_t)(mbar)) : "memory")

// ---------------------------------------------------------------------------
// Kernel 1: merged prep, grid (32, 32, 3), 256 threads.
//   z==0: x -> fp16 + pooled partials.
//   z==1 (g<512): streaming convert W1 f32 -> fp16.
//   z==2 (y==0, x<32): router for batch x, gated on all z==0 blocks done.
// ---------------------------------------------------------------------------
__global__ __launch_bounds__(256)
void prep_kernel(const float* __restrict__ x,
                 __half* __restrict__ xh,
                 float* __restrict__ pool_part,
                 const float* __restrict__ W1,
                 __half* __restrict__ W1h,
                 const float* __restrict__ Wp,
                 const float* __restrict__ bp,
                 float* __restrict__ probs_out,
                 float* __restrict__ chosen_out)
{
    if (blockIdx.z == 0) {
        const int b  = blockIdx.x;
        const int tc = blockIdx.y;
        const int d0 = threadIdx.x * 2;

        float s0 = 0.0f, s1 = 0.0f;
        #pragma unroll 4
        for (int r = 0; r < 16; ++r) {
            const int t = tc * 16 + r;
            const size_t off = ((size_t)b * T_ + t) * D_ + d0;
            const float2 v = *reinterpret_cast<const float2*>(x + off);
            s0 += v.x; s1 += v.y;
            *reinterpret_cast<__half2*>(xh + off) =
                __halves2half2(__float2half_rn(v.x), __float2half_rn(v.y));
        }
        *reinterpret_cast<float2*>(pool_part + ((size_t)b * 32 + tc) * D_ + d0) =
            make_float2(s0, s1);
        __threadfence();
        __syncthreads();
        if (threadIdx.x == 0) atomicAdd(&g_prep_done, 1);
        return;
    }

    if (blockIdx.z == 2) {
        if (blockIdx.y != 0 || blockIdx.x >= B_) return;
        const int b = blockIdx.x;

        if (threadIdx.x == 0) {
            while (*(volatile int*)&g_prep_done < 32 * 32) __nanosleep(100);
        }
        __syncthreads();
        __threadfence();

        __shared__ float pooled[D_];
        __shared__ float logits[E_];
        #pragma unroll
        for (int k = 0; k < 2; ++k) {
            const int d = threadIdx.x + k * 256;
            float s = 0.0f;
            #pragma unroll
            for (int p = 0; p < 32; ++p)
                s += pool_part[((size_t)b * 32 + p) * D_ + d];
            pooled[d] = s * (1.0f / (float)T_);
        }
        __syncthreads();

        const int warp = threadIdx.x >> 5, lane = threadIdx.x & 31;
        {
            float s = 0.0f;
            #pragma unroll
            for (int k = 0; k < 16; ++k) {
                const int dd = lane + k * 32;
                s += pooled[dd] * Wp[dd * E_ + warp];
            }
            #pragma unroll
            for (int off = 16; off > 0; off >>= 1)
                s += __shfl_down_sync(0xffffffffu, s, off);
            if (lane == 0) logits[warp] = s + bp[warp];
        }
        __syncthreads();

        if (threadIdx.x == 0) {
            float m = logits[0]; int arg = 0;
            #pragma unroll
            for (int e = 1; e < E_; ++e)
                if (logits[e] > m) { m = logits[e]; arg = e; }
            float ex[E_], sum = 0.0f;
            #pragma unroll
            for (int e = 0; e < E_; ++e) { ex[e] = expf(logits[e] - m); sum += ex[e]; }
            const float inv = 1.0f / sum;
            if (probs_out) {
                #pragma unroll
                for (int e = 0; e < E_; ++e) probs_out[b * E_ + e] = ex[e] * inv;
            }
            if (chosen_out) chosen_out[b] = (float)arg;
            g_chosen[b] = arg;
        }
        return;
    }

    // ---- z==1: streaming W1 convert (first 512 blocks only) ----
    {
        const int g = blockIdx.y * 32 + blockIdx.x;
        if (g >= 512) return;
        const float* src = W1 + (size_t)g * 16384;
        __half* dst = W1h + (size_t)g * 16384;
        #pragma unroll
        for (int i = 0; i < 16; ++i) {
            const int idx = (threadIdx.x + i * 256) * 4;
            const float4 v = *reinterpret_cast<const float4*>(src + idx);
            __half2 h0 = __halves2half2(__float2half_rn(v.x), __float2half_rn(v.y));
            __half2 h1 = __halves2half2(__float2half_rn(v.z), __float2half_rn(v.w));
            uint2 pk;
            pk.x = *reinterpret_cast<uint32_t*>(&h0);
            pk.y = *reinterpret_cast<uint32_t*>(&h1);
            *reinterpret_cast<uint2*>(dst + idx) = pk;
        }
    }
}

// ---------------------------------------------------------------------------
// Kernel 2: batched expert GEMM with TMA operand loads + PDL.
//   G1: grid (16, 4, 36). z<4 -> W2 streaming convert (256 early blocks).
//       z>=4 -> GEMM for batch b = z-4.
//   G2: grid (4, 4, 32), plain GEMM, b = z.
// All paths griddepcontrol.wait on the upstream kernel before touching its
// outputs (and before the g_prep_done replay reset — PDL allows pre-wait code
// to run before the primary completes).
// ---------------------------------------------------------------------------
#define STAGE_BYTES 32768
#define MBAR_OFF    (3 * STAGE_BYTES)
#define GEMM_SMEM   (MBAR_OFF + 128)

template <bool G1>   // true: relu + fp16 out; false: f32 out
__global__ __launch_bounds__(256, 2)
void moe_gemm_kernel(const __grid_constant__ CUtensorMap tmA,
                     const __grid_constant__ CUtensorMap tmB,
                     const float* __restrict__ biasAll,
                     float* __restrict__ outF,
                     __half* __restrict__ outH,
                     int K, int Nt,
                     const float* __restrict__ W2src,
                     __half* __restrict__ W2h)
{
    extern __shared__ char smem[];

    GRIDDEP_WAIT();   // upstream kernel (prep / GEMM1) fully done + visible

    int b = blockIdx.z;
    if (G1) {
        if (blockIdx.z < 4) {
            // ---- W2 streaming convert: 256 blocks x 32768 f32 ----
            const int g = blockIdx.z * 64 + blockIdx.y * 16 + blockIdx.x;  // 0..255
            const float* src = W2src + (size_t)g * 32768;
            __half* dst = W2h + (size_t)g * 32768;
            #pragma unroll
            for (int i = 0; i < 32; ++i) {
                const int idx = (threadIdx.x + i * 256) * 4;
                const float4 v = *reinterpret_cast<const float4*>(src + idx);
                __half2 h0 = __halves2half2(__float2half_rn(v.x), __float2half_rn(v.y));
                __half2 h1 = __halves2half2(__float2half_rn(v.z), __float2half_rn(v.w));
                uint2 pk;
                pk.x = *reinterpret_cast<uint32_t*>(&h0);
                pk.y = *reinterpret_cast<uint32_t*>(&h1);
                *reinterpret_cast<uint2*>(dst + idx) = pk;
            }
            return;
        }
        b = blockIdx.z - 4;
        // graph-replay counter reset — safe: after griddepcontrol.wait
        if (blockIdx.x == 0 && blockIdx.y == 0 && b == 0 && threadIdx.x == 0)
            g_prep_done = 0;
    }

    const uint32_t sbase = smem_to_u32(smem);
    const int tid  = threadIdx.x;
    const int lane = tid & 31;
    const int wid  = tid >> 5;
    const int warp_m = wid & 1;          // 2 warps along M (64 each)
    const int warp_n = wid >> 1;         // 4 warps along N (32 each)

    const int e  = g_chosen[b];
    const int m0 = blockIdx.y * 128;
    const int n0 = blockIdx.x * 128;

    // A ldmatrix addressing (128B rows, SW128: c16 ^= row&7)
    const int ltile = lane >> 3;
    const int lr    = lane & 7;
    const uint32_t xr = (uint32_t)lr << 4;
    const uint32_t baseA = (uint32_t)(warp_m * 64 + (ltile & 1) * 8 + lr) * 128u;
    const uint32_t kcA   = (uint32_t)(ltile >> 1) * 16u;

    // B ldmatrix.trans addressing: half = warp_n>>1, 64-row x 128B blocks.
    const uint32_t bOff = 16384u + (uint32_t)(warp_n >> 1) * 8192u;
    const uint32_t rowL = (uint32_t)((ltile & 1) * 8 + lr);
    const uint32_t cb0  = (uint32_t)((warp_n & 1) * 4 + (ltile >> 1));
    const uint32_t addrB0 = bOff + rowL * 128u + ((cb0 ^ (uint32_t)lr) << 4);
    const uint32_t addrB1 = bOff + rowL * 128u + (((cb0 + 2u) ^ (uint32_t)lr) << 4);

    float acc[4][4][4];
    #pragma unroll
    for (int mi = 0; mi < 4; ++mi)
        #pragma unroll
        for (int ni = 0; ni < 4; ++ni)
            #pragma unroll
            for (int i = 0; i < 4; ++i) acc[mi][ni][i] = 0.0f;

    const int KB = K >> 6;
    const uint32_t mbar0 = sbase + MBAR_OFF;

    auto issue_stage = [&](int s, int kb2) {
        const uint32_t stg = sbase + (uint32_t)s * STAGE_BYTES;
        const uint32_t mb  = mbar0 + (uint32_t)s * 8u;
        const int k0 = kb2 << 6;
        MBARRIER_EXPECT_TX(mb, STAGE_BYTES);
        TMA_LOAD_3D(stg,           &tmA, k0,       m0, b, mb);
        TMA_LOAD_3D(stg + 16384u,  &tmB, n0,       k0, e, mb);
        TMA_LOAD_3D(stg + 24576u,  &tmB, n0 + 64,  k0, e, mb);
    };

    if (tid == 0) {
        MBARRIER_INIT(mbar0 + 0, 1);
        MBARRIER_INIT(mbar0 + 8, 1);
        MBARRIER_INIT(mbar0 + 16, 1);
        asm volatile("fence.proxy.async.shared::cta;" ::: "memory");
    }
    __syncthreads();
    if (tid == 0) {
        issue_stage(0, 0);
        issue_stage(1, 1);
    }

    uint32_t af[2][4][4], bf[4][2];

    auto load_af = [&](int buf, uint32_t stg, int kk) {
        const uint32_t kA = ((uint32_t)(kk * 32) + kcA) ^ xr;
        #pragma unroll
        for (int mi = 0; mi < 4; ++mi)
            ldsm4(af[buf][mi], stg + baseA + mi * 2048u + kA);
    };
    auto load_bf = [&](uint32_t stg, int kk) {
        const uint32_t kOff = (uint32_t)kk * 2048u;   // 16 k-rows * 128B
        uint32_t t4[4];
        ldsm4t(t4, stg + kOff + addrB0);
        bf[0][0] = t4[0]; bf[0][1] = t4[1];
        bf[1][0] = t4[2]; bf[1][1] = t4[3];
        ldsm4t(t4, stg + kOff + addrB1);
        bf[2][0] = t4[0]; bf[2][1] = t4[1];
        bf[3][0] = t4[2]; bf[3][1] = t4[3];
    };

    for (int kb = 0; kb < KB; ++kb) {
        const int s = kb % 3;
        const int par = (kb / 3) & 1;
        MBARRIER_WAIT_PARITY(mbar0 + (uint32_t)s * 8u, par);
        if (tid == 0 && kb + 2 < KB) issue_stage((kb + 2) % 3, kb + 2);

        const uint32_t stg = sbase + (uint32_t)s * STAGE_BYTES;

        load_af(0, stg, 0);
        #pragma unroll
        for (int kk = 0; kk < 4; ++kk) {
            load_bf(stg, kk);
            if (kk < 3) load_af((kk + 1) & 1, stg, kk + 1);
            #pragma unroll
            for (int mi = 0; mi < 4; ++mi)
                #pragma unroll
                for (int ni = 0; ni < 4; ++ni)
                    mma16816(acc[mi][ni], af[kk & 1][mi], bf[ni]);
        }
        __syncthreads();   // stage consumed; safe for TMA overwrite next iters
    }

    // ---- epilogue ----
    const int gm = m0 + warp_m * 64;
    const int gncol = n0 + warp_n * 32;
    #pragma unroll
    for (int mi = 0; mi < 4; ++mi) {
        const int row0 = gm + mi * 16 + (lane >> 2);
        #pragma unroll
        for (int ni = 0; ni < 4; ++ni) {
            const int col = gncol + ni * 8 + (lane & 3) * 2;
            const float2 bv = *reinterpret_cast<const float2*>(
                biasAll + (size_t)e * Nt + col);
            float v00 = acc[mi][ni][0] + bv.x;
            float v01 = acc[mi][ni][1] + bv.y;
            float v10 = acc[mi][ni][2] + bv.x;
            float v11 = acc[mi][ni][3] + bv.y;
            const size_t o0 = ((size_t)b * T_ + row0) * Nt + col;
            const size_t o1 = ((size_t)b * T_ + row0 + 8) * Nt + col;
            if (G1) {
                v00 = fmaxf(v00, 0.0f); v01 = fmaxf(v01, 0.0f);
                v10 = fmaxf(v10, 0.0f); v11 = fmaxf(v11, 0.0f);
                *reinterpret_cast<__half2*>(outH + o0) =
                    __halves2half2(__float2half_rn(v00), __float2half_rn(v01));
                *reinterpret_cast<__half2*>(outH + o1) =
                    __halves2half2(__float2half_rn(v10), __float2half_rn(v11));
            } else {
                *reinterpret_cast<float2*>(outF + o0) = make_float2(v00, v01);
                *reinterpret_cast<float2*>(outF + o1) = make_float2(v10, v11);
            }
        }
    }
}

// ---------------------------------------------------------------------------
// Host: tensormap encoding via driver entry point
// ---------------------------------------------------------------------------
typedef CUresult (*EncFn)(CUtensorMap*, CUtensorMapDataType, cuuint32_t, void*,
                          const cuuint64_t*, const cuuint64_t*, const cuuint32_t*,
                          const cuuint32_t*, CUtensorMapInterleave,
                          CUtensorMapSwizzle, CUtensorMapL2promotion,
                          CUtensorMapFloatOOBfill);

static EncFn get_encoder()
{
    void* fn = nullptr;
    cudaDriverEntryPointQueryResult st;
#if CUDART_VERSION >= 12050
    cudaGetDriverEntryPointByVersion("cuTensorMapEncodeTiled", &fn, 12000,
                                     cudaEnableDefault, &st);
#else
    cudaGetDriverEntryPoint("cuTensorMapEncodeTiled", &fn,
                            cudaEnableDefault, &st);
#endif
    return (EncFn)fn;
}

static void make_tmap(EncFn enc, CUtensorMap* tm, void* base,
                      uint64_t d0, uint64_t d1, uint64_t d2,
                      uint32_t box0, uint32_t box1)
{
    cuuint64_t dims[3]    = {d0, d1, d2};
    cuuint64_t strides[2] = {d0 * 2, d0 * d1 * 2};
    cuuint32_t box[3]     = {box0, box1, 1};
    cuuint32_t es[3]      = {1, 1, 1};
    enc(tm, CU_TENSOR_MAP_DATA_TYPE_FLOAT16, 3, base, dims, strides, box, es,
        CU_TENSOR_MAP_INTERLEAVE_NONE, CU_TENSOR_MAP_SWIZZLE_128B,
        CU_TENSOR_MAP_L2_PROMOTION_L2_128B, CU_TENSOR_MAP_FLOAT_OOB_FILL_NONE);
}

// ---------------------------------------------------------------------------
// kernel_launch
// ---------------------------------------------------------------------------
extern "C" void kernel_launch(void* const* d_in, const int* in_sizes, int n_in,
                              void* d_out, int out_size)
{
    const float* x  = (const float*)d_in[0];
    const float* Wp = (const float*)d_in[1];
    const float* bp = (const float*)d_in[2];
    const float* W1 = (const float*)d_in[3];
    const float* b1 = (const float*)d_in[4];
    const float* W2 = (const float*)d_in[5];
    const float* b2 = (const float*)d_in[6];
    float* out = (float*)d_out;

    const long long FINAL_N = (long long)B_ * T_ * D_;
    float* probs_out  = nullptr;
    float* chosen_out = nullptr;
    if ((long long)out_size >= FINAL_N + (long long)B_ * E_)
        probs_out = out + FINAL_N;
    if ((long long)out_size >= FINAL_N + (long long)B_ * E_ + B_)
        chosen_out = out + FINAL_N + (long long)B_ * E_;

    __half *xh, *hh, *w1h, *w2h;
    float* pool_part;
    cudaGetSymbolAddress((void**)&xh, g_x_h);
    cudaGetSymbolAddress((void**)&hh, g_h_h);
    cudaGetSymbolAddress((void**)&w1h, g_W1h);
    cudaGetSymbolAddress((void**)&w2h, g_W2h);
    cudaGetSymbolAddress((void**)&pool_part, g_pool_part);

    EncFn enc = get_encoder();
    CUtensorMap tmA1, tmB1, tmA2, tmB2;
    make_tmap(enc, &tmA1, xh,  512, 512, 32, 64, 128);     // A1: (K,T,B)
    make_tmap(enc, &tmB1, w1h, 2048, 512, 8, 64, 64);      // B1: (N,K,E)
    make_tmap(enc, &tmA2, hh,  2048, 512, 32, 64, 128);    // A2
    make_tmap(enc, &tmB2, w2h, 512, 2048, 8, 64, 64);      // B2

    cudaFuncSetAttribute(moe_gemm_kernel<true>,
                         cudaFuncAttributeMaxDynamicSharedMemorySize, GEMM_SMEM);
    cudaFuncSetAttribute(moe_gemm_kernel<false>,
                         cudaFuncAttributeMaxDynamicSharedMemorySize, GEMM_SMEM);

    // 1) prep: x->fp16 + pool partials (z=0), W1 convert (z=1), router (z=2)
    prep_kernel<<<dim3(32, 32, 3), 256>>>(x, xh, pool_part, W1, w1h,
                                          Wp, bp, probs_out, chosen_out);

    // PDL attribute for the two GEMM launches
    cudaLaunchAttribute pdl[1];
    pdl[0].id = cudaLaunchAttributeProgrammaticStreamSerialization;
    pdl[0].val.programmaticStreamSerializationAllowed = 1;

    // 2) GEMM1 (+early W2 convert blocks at z<4), PDL behind prep
    {
        cudaLaunchConfig_t cfg = {};
        cfg.gridDim = dim3(H_ / 128, T_ / 128, B_ + 4);
        cfg.blockDim = dim3(256);
        cfg.dynamicSmemBytes = GEMM_SMEM;
        cfg.stream = 0;
        cfg.attrs = pdl;
        cfg.numAttrs = 1;
        cudaLaunchKernelEx(&cfg, moe_gemm_kernel<true>,
                           tmA1, tmB1, (const float*)b1, (float*)nullptr,
                           (__half*)hh, (int)D_, (int)H_,
                           (const float*)W2, (__half*)w2h);
    }

    // 3) GEMM2, PDL behind GEMM1
    {
        cudaLaunchConfig_t cfg = {};
        cfg.gridDim = dim3(D_ / 128, T_ / 128, B_);
        cfg.blockDim = dim3(256);
        cfg.dynamicSmemBytes = GEMM_SMEM;
        cfg.stream = 0;
        cfg.attrs = pdl;
        cfg.numAttrs = 1;
        cudaLaunchKernelEx(&cfg, moe_gemm_kernel<false>,
                           tmA2, tmB2, (const float*)b2, (float*)out,
                           (__half*)nullptr, (int)H_, (int)D_,
                           (const float*)nullptr, (__half*)nullptr);
    }
}